// round 10
// baseline (speedup 1.0000x reference)
#include <cuda_runtime.h>
#include <cstdint>

// Problem constants (fixed by the reference)
#define H            8
#define NUM_DRAM     4096
#define NUM_HBM      819          // int(4096 * 0.2)
#define TOPK         256
#define PAGE_SIZE    16
#define HEAD_DIM     128
#define PAGE_ELEMS   4096         // 16 * 2 * 128
#define SEQ_PER_HEAD (NUM_HBM * PAGE_SIZE)              // 13104
#define KELEMS_HEAD  ((size_t)SEQ_PER_HEAD * HEAD_DIM)  // 1,677,312
#define KTOTAL       ((size_t)H * KELEMS_HEAD)          // 13,418,496

#define GRID_BLOCKS    1184       // 148 SMs * 8 blocks: guaranteed co-resident
#define CHUNKS_PER_H   26         // 26 chunks x 32 slots >= 819
#define SETUP_BLOCKS   (H * CHUNKS_PER_H)   // 208
#define SLOTS_PER_WARP 4          // 8 warps * 4 = 32 slots per setup block

// Scratch (device globals: allocation-free; g_done monotonic => replay-safe)
__device__ int g_src_page[H * NUM_HBM];          // -1 => keep hbm page
__device__ unsigned long long g_done = 0ULL;     // setup blocks arrive once each

// ---------------------------------------------------------------------------
// ONE persistent kernel: setup (blocks 0..207) -> done-count wait -> copy.
//
// Epoch WITHOUT a per-block atomic (R9 lesson: 1184 contended atomicAdds on
// one address serialize at ~27cyc/op => ~10us stall). Every block instead
// does a plain load done0 = g_done as its first action. Setup blocks are the
// lowest bids (launched first, ramp ~0.6us << setup ~3us), so every block
// reads done0 BEFORE this replay's 208 arrivals complete:
//   target = (done0/208 + 1) * 208   -- floor() absorbs partial arrivals.
// Counter is never reset -> deterministic across CUDA-graph replays.
//
// Setup emulates the reference exactly, incl. JAX's negative-index WRAPPING
// in scatters (idx=-1 -> slot 818, applied before mode='drop'):
//   slot = d2h[topk];  pat[slot>=0 ? slot : 818] = step_f
//   stable rank(i) over pat; slot i is a victim iff rank(i) < n_miss,
//   receiving the page of the rank(i)-th miss (inverse of order[] scatter).
//   Hits scatter to wrapped slot 818, last hit wins (818 is never a victim:
//   pat[818]==step_f puts its rank above any possible n_miss).
// ---------------------------------------------------------------------------
__global__ void __launch_bounds__(256, 8) lru_fused_kernel(
    const float* __restrict__ dram,
    const float* __restrict__ hbm,
    const float* __restrict__ pat_g,
    const int*   __restrict__ d2h_g,
    const int*   __restrict__ topk_g,
    const int*   __restrict__ step_g,
    float*       __restrict__ kout,
    float*       __restrict__ vout)
{
    __shared__ float pat_s[NUM_HBM];
    __shared__ int   miss_page[TOPK];
    __shared__ int   warp_pre[TOPK / 32];
    __shared__ int   n_miss_s, last_hit_s, last_hit_page_s;
    __shared__ unsigned long long target_s;

    const int b    = blockIdx.x;
    const int t    = threadIdx.x;
    const int warp = t >> 5;
    const int lane = t & 31;

    // First action: capture barrier generation via a PLAIN load (no atomic).
    if (t == 0) {
        const unsigned long long done0 =
            *((volatile unsigned long long*)&g_done);
        target_s = (done0 / (unsigned long long)SETUP_BLOCKS + 1ULL)
                   * (unsigned long long)SETUP_BLOCKS;
    }

    // ---------------- Phase 1: setup (blocks 0..207) ----------------
    if (b < SETUP_BLOCKS) {
        const int h     = b / CHUNKS_PER_H;
        const int chunk = b - h * CHUNKS_PER_H;
        const float step_f = (float)(step_g[0] + 1);

        if (t == 0) { last_hit_s = -1; last_hit_page_s = -1; }
        for (int i = t; i < NUM_HBM; i += 256)
            pat_s[i] = pat_g[h * NUM_HBM + i];

        // Each thread owns one topk entry
        const int p    = topk_g[h * TOPK + t];
        const int slot = d2h_g[h * NUM_DRAM + p];
        const bool miss = (slot < 0);
        const unsigned mm = __ballot_sync(0xFFFFFFFFu, miss);
        const int wpre = __popc(mm & ((1u << lane) - 1u));
        if (lane == 0) warp_pre[warp] = __popc(mm);
        if (!miss) atomicMax(&last_hit_s, t);
        __syncthreads();

        // pat scatter with wrapped negative index (all writes = step_f)
        pat_s[miss ? (NUM_HBM - 1) : slot] = step_f;
        if (t == 0) {
            int c = 0;
            #pragma unroll
            for (int w = 0; w < TOPK / 32; w++) { const int x = warp_pre[w]; warp_pre[w] = c; c += x; }
            n_miss_s = c;
        }
        __syncthreads();

        if (miss) miss_page[warp_pre[warp] + wpre] = p;
        if (t == last_hit_s) last_hit_page_s = p;
        __syncthreads();

        // Each warp ranks 4 slots in one sweep over pat_s.
        float vi[SLOTS_PER_WARP];
        int   r [SLOTS_PER_WARP];
        int   idx[SLOTS_PER_WARP];
        #pragma unroll
        for (int q = 0; q < SLOTS_PER_WARP; q++) {
            idx[q] = chunk * 32 + warp * SLOTS_PER_WARP + q;
            vi[q]  = (idx[q] < NUM_HBM) ? pat_s[idx[q]] : 0.0f;
            r[q]   = 0;
        }
        #pragma unroll 2
        for (int j = lane; j < NUM_HBM; j += 32) {
            const float vj = pat_s[j];
            #pragma unroll
            for (int q = 0; q < SLOTS_PER_WARP; q++)
                r[q] += (vj < vi[q]) || (vj == vi[q] && j < idx[q]);
        }
        #pragma unroll
        for (int q = 0; q < SLOTS_PER_WARP; q++) {
            const int rq = __reduce_add_sync(0xFFFFFFFFu, r[q]);
            if (lane == 0 && idx[q] < NUM_HBM) {
                int sp = (rq < n_miss_s) ? miss_page[rq] : -1;
                if (idx[q] == NUM_HBM - 1 && last_hit_page_s >= 0) sp = last_hit_page_s;
                g_src_page[h * NUM_HBM + idx[q]] = sp;
            }
        }
        __syncthreads();           // all warps' g_src_page writes done

        if (t == 0) {
            __threadfence();       // release g_src_page
            atomicAdd(&g_done, 1ULL);   // only 208 contended atomics total
        }
    }

    // ---------------- Wait for all setup arrivals (t==0 only) --------------
    if (t == 0) {
        const unsigned long long target = target_s;
        volatile unsigned long long* ctr = &g_done;
        if (*ctr < target) {
            if (b >= SETUP_BLOCKS) __nanosleep(1000);   // setup takes ~2-3us
            unsigned ns = 64;
            while (*ctr < target) {
                __nanosleep(ns);
                if (ns < 512) ns <<= 1;
            }
        }
        __threadfence();           // acquire
    }
    __syncthreads();

    // ---------------- Phase 2: bulk de-interleaving copy ----------------
    // src elem e = row*256 + kv*128 + d  ->  k/v[h, s*16+row, d].
    for (int page_id = b; page_id < H * NUM_HBM; page_id += GRID_BLOCKS) {
        const int h = page_id / NUM_HBM;
        const int s = page_id - h * NUM_HBM;

        const int sp = g_src_page[page_id];
        const float4* __restrict__ src = (const float4*)(
            (sp >= 0) ? (dram + ((size_t)h * NUM_DRAM + (size_t)sp) * PAGE_ELEMS)
                      : (hbm  + (size_t)page_id * PAGE_ELEMS));

        float4* __restrict__ kbase =
            (float4*)(kout + ((size_t)h * SEQ_PER_HEAD + (size_t)s * PAGE_SIZE) * HEAD_DIM);
        float4* __restrict__ vbase =
            (float4*)(vout + ((size_t)h * SEQ_PER_HEAD + (size_t)s * PAGE_SIZE) * HEAD_DIM);

        // 1024 float4 per page; 4 independent 16B ops per thread (MLP=4).
        #pragma unroll
        for (int u = 0; u < 4; u++) {
            const int f = t + u * 256;
            const float4 val = src[f];
            const int row = f >> 6;
            const int dd  = f & 31;
            if ((f >> 5) & 1) vbase[row * 32 + dd] = val;
            else              kbase[row * 32 + dd] = val;
        }
    }
}

// ---------------------------------------------------------------------------
// Launch: single kernel, graph-capture friendly, allocation-free.
// ---------------------------------------------------------------------------
extern "C" void kernel_launch(void* const* d_in, const int* in_sizes, int n_in,
                              void* d_out, int out_size)
{
    const float* dram = (const float*)d_in[0];   // (H, 4096, 4096) f32
    const float* hbm  = (const float*)d_in[1];   // (H, 819, 4096)  f32
    const float* pat  = (const float*)d_in[2];   // (H, 819)        f32
    const int*   d2h  = (const int*)  d_in[3];   // (H, 4096)       i32
    // d_in[4] = h2d (never affects the returned k/v caches)
    const int*   topk = (const int*)  d_in[5];   // (H, 256)        i32
    const int*   step = (const int*)  d_in[6];   // (1,)            i32

    float* kout = (float*)d_out;
    float* vout = (float*)d_out + KTOTAL;

    lru_fused_kernel<<<GRID_BLOCKS, 256>>>(dram, hbm, pat, d2h, topk, step, kout, vout);
}

// round 11
// speedup vs baseline: 1.0110x; 1.0110x over previous
#include <cuda_runtime.h>
#include <cstdint>

// Problem constants (fixed by the reference)
#define H            8
#define NUM_DRAM     4096
#define NUM_HBM      819          // int(4096 * 0.2)
#define TOPK         256
#define PAGE_SIZE    16
#define HEAD_DIM     128
#define PAGE_ELEMS   4096         // 16 * 2 * 128
#define SEQ_PER_HEAD (NUM_HBM * PAGE_SIZE)              // 13104
#define KELEMS_HEAD  ((size_t)SEQ_PER_HEAD * HEAD_DIM)  // 1,677,312
#define KTOTAL       ((size_t)H * KELEMS_HEAD)          // 13,418,496

#define GRID_BLOCKS    1184       // 148 SMs * 8 blocks: guaranteed co-resident
#define CHUNKS_PER_H   26         // 26 chunks x 32 slots >= 819
#define SETUP_BLOCKS   (H * CHUNKS_PER_H)   // 208
#define SLOTS_PER_WARP 4          // 8 warps * 4 = 32 slots per setup block
#define FLAG_STRIDE    32         // 32 u32 = 128B: one L2 line per flag

// Scratch (device globals: allocation-free; all counters monotonic => replay-safe)
__device__ int g_src_page[H * NUM_HBM];              // -1 => keep hbm page
__device__ unsigned long long g_done = 0ULL;         // setup arrivals (cumulative)
__device__ unsigned g_flag[GRID_BLOCKS * FLAG_STRIDE]; // per-block release flags (epoch)

// ---------------------------------------------------------------------------
// ONE persistent kernel: setup (blocks 0..207) -> distributed-flag barrier ->
// grid-stride copy (all 1184 blocks).
//
// Barrier (R10 lesson): polling ONE address from 1184 blocks saturates a
// single L2 slice (>2 loads/ns vs ~1.8/ns service) no matter the backoff,
// queueing the release store behind the storm. Here every block polls ITS
// OWN 128B-strided flag (1 poller per line => no contention). The 208th
// setup arrival -- detected from the atomicAdd return, no polling -- has its
// whole block write all 1184 flags in parallel (<0.5us). Flags carry a
// monotonic epoch; target = own_flag + 1 captured via plain load at block
// start (ramp ~1us << setup ~3us, so always pre-release). Deterministic
// across CUDA-graph replays.
//
// Setup emulates the reference exactly, incl. JAX's negative-index WRAPPING
// in scatters (idx=-1 -> slot 818, applied before mode='drop'):
//   slot = d2h[topk];  pat[slot>=0 ? slot : 818] = step_f
//   stable rank(i) over pat; slot i is a victim iff rank(i) < n_miss,
//   receiving the page of the rank(i)-th miss (inverse of order[] scatter).
//   Hits scatter to wrapped slot 818, last hit wins (818 is never a victim:
//   pat[818]==step_f puts its rank above any possible n_miss).
// ---------------------------------------------------------------------------
__global__ void __launch_bounds__(256, 8) lru_fused_kernel(
    const float* __restrict__ dram,
    const float* __restrict__ hbm,
    const float* __restrict__ pat_g,
    const int*   __restrict__ d2h_g,
    const int*   __restrict__ topk_g,
    const int*   __restrict__ step_g,
    float*       __restrict__ kout,
    float*       __restrict__ vout)
{
    __shared__ float pat_s[NUM_HBM];
    __shared__ int   miss_page[TOPK];
    __shared__ int   warp_pre[TOPK / 32];
    __shared__ int   n_miss_s, last_hit_s, last_hit_page_s;
    __shared__ unsigned target_s;
    __shared__ unsigned long long old_s;

    const int b    = blockIdx.x;
    const int t    = threadIdx.x;
    const int warp = t >> 5;
    const int lane = t & 31;

    // First action: capture this block's release target via a PLAIN load.
    if (t == 0)
        target_s = *((volatile unsigned*)&g_flag[b * FLAG_STRIDE]) + 1u;

    // ---------------- Phase 1: setup (blocks 0..207) ----------------
    if (b < SETUP_BLOCKS) {
        const int h     = b / CHUNKS_PER_H;
        const int chunk = b - h * CHUNKS_PER_H;
        const float step_f = (float)(step_g[0] + 1);

        if (t == 0) { last_hit_s = -1; last_hit_page_s = -1; }
        for (int i = t; i < NUM_HBM; i += 256)
            pat_s[i] = pat_g[h * NUM_HBM + i];

        // Each thread owns one topk entry
        const int p    = topk_g[h * TOPK + t];
        const int slot = d2h_g[h * NUM_DRAM + p];
        const bool miss = (slot < 0);
        const unsigned mm = __ballot_sync(0xFFFFFFFFu, miss);
        const int wpre = __popc(mm & ((1u << lane) - 1u));
        if (lane == 0) warp_pre[warp] = __popc(mm);
        if (!miss) atomicMax(&last_hit_s, t);
        __syncthreads();

        // pat scatter with wrapped negative index (all writes = step_f)
        pat_s[miss ? (NUM_HBM - 1) : slot] = step_f;
        if (t == 0) {
            int c = 0;
            #pragma unroll
            for (int w = 0; w < TOPK / 32; w++) { const int x = warp_pre[w]; warp_pre[w] = c; c += x; }
            n_miss_s = c;
        }
        __syncthreads();

        if (miss) miss_page[warp_pre[warp] + wpre] = p;
        if (t == last_hit_s) last_hit_page_s = p;
        __syncthreads();

        // Each warp ranks 4 slots in one sweep over pat_s.
        float vi[SLOTS_PER_WARP];
        int   r [SLOTS_PER_WARP];
        int   idx[SLOTS_PER_WARP];
        #pragma unroll
        for (int q = 0; q < SLOTS_PER_WARP; q++) {
            idx[q] = chunk * 32 + warp * SLOTS_PER_WARP + q;
            vi[q]  = (idx[q] < NUM_HBM) ? pat_s[idx[q]] : 0.0f;
            r[q]   = 0;
        }
        #pragma unroll 2
        for (int j = lane; j < NUM_HBM; j += 32) {
            const float vj = pat_s[j];
            #pragma unroll
            for (int q = 0; q < SLOTS_PER_WARP; q++)
                r[q] += (vj < vi[q]) || (vj == vi[q] && j < idx[q]);
        }
        #pragma unroll
        for (int q = 0; q < SLOTS_PER_WARP; q++) {
            const int rq = __reduce_add_sync(0xFFFFFFFFu, r[q]);
            if (lane == 0 && idx[q] < NUM_HBM) {
                int sp = (rq < n_miss_s) ? miss_page[rq] : -1;
                if (idx[q] == NUM_HBM - 1 && last_hit_page_s >= 0) sp = last_hit_page_s;
                g_src_page[h * NUM_HBM + idx[q]] = sp;
            }
        }
        __syncthreads();           // all warps' g_src_page writes done

        if (t == 0) {
            __threadfence();       // release g_src_page before arrival
            old_s = atomicAdd(&g_done, 1ULL);
        }
        __syncthreads();

        // Last arriving setup block releases everyone: write all flags in
        // parallel with the whole block (distributed, one line per flag).
        if (old_s % (unsigned long long)SETUP_BLOCKS ==
            (unsigned long long)(SETUP_BLOCKS - 1)) {
            const unsigned epoch1 =
                (unsigned)(old_s / (unsigned long long)SETUP_BLOCKS) + 1u;
            __threadfence();       // order after observing all arrivals
            for (int i = t; i < GRID_BLOCKS; i += 256)
                *((volatile unsigned*)&g_flag[i * FLAG_STRIDE]) = epoch1;
        }
    }

    // ---------------- Wait: each block polls its OWN flag ----------------
    if (t == 0) {
        volatile unsigned* f = &g_flag[b * FLAG_STRIDE];
        const unsigned target = target_s;
        while (*f < target) __nanosleep(128);
        __threadfence();           // acquire g_src_page
    }
    __syncthreads();

    // ---------------- Phase 2: bulk de-interleaving copy ----------------
    // src elem e = row*256 + kv*128 + d  ->  k/v[h, s*16+row, d].
    for (int page_id = b; page_id < H * NUM_HBM; page_id += GRID_BLOCKS) {
        const int h = page_id / NUM_HBM;
        const int s = page_id - h * NUM_HBM;

        const int sp = g_src_page[page_id];
        const float4* __restrict__ src = (const float4*)(
            (sp >= 0) ? (dram + ((size_t)h * NUM_DRAM + (size_t)sp) * PAGE_ELEMS)
                      : (hbm  + (size_t)page_id * PAGE_ELEMS));

        float4* __restrict__ kbase =
            (float4*)(kout + ((size_t)h * SEQ_PER_HEAD + (size_t)s * PAGE_SIZE) * HEAD_DIM);
        float4* __restrict__ vbase =
            (float4*)(vout + ((size_t)h * SEQ_PER_HEAD + (size_t)s * PAGE_SIZE) * HEAD_DIM);

        // 1024 float4 per page; 4 independent 16B ops per thread (MLP=4).
        #pragma unroll
        for (int u = 0; u < 4; u++) {
            const int f = t + u * 256;
            const float4 val = src[f];
            const int row = f >> 6;
            const int dd  = f & 31;
            if ((f >> 5) & 1) vbase[row * 32 + dd] = val;
            else              kbase[row * 32 + dd] = val;
        }
    }
}

// ---------------------------------------------------------------------------
// Launch: single kernel, graph-capture friendly, allocation-free.
// ---------------------------------------------------------------------------
extern "C" void kernel_launch(void* const* d_in, const int* in_sizes, int n_in,
                              void* d_out, int out_size)
{
    const float* dram = (const float*)d_in[0];   // (H, 4096, 4096) f32
    const float* hbm  = (const float*)d_in[1];   // (H, 819, 4096)  f32
    const float* pat  = (const float*)d_in[2];   // (H, 819)        f32
    const int*   d2h  = (const int*)  d_in[3];   // (H, 4096)       i32
    // d_in[4] = h2d (never affects the returned k/v caches)
    const int*   topk = (const int*)  d_in[5];   // (H, 256)        i32
    const int*   step = (const int*)  d_in[6];   // (1,)            i32

    float* kout = (float*)d_out;
    float* vout = (float*)d_out + KTOTAL;

    lru_fused_kernel<<<GRID_BLOCKS, 256>>>(dram, hbm, pat, d2h, topk, step, kout, vout);
}

// round 12
// speedup vs baseline: 1.0195x; 1.0085x over previous
#include <cuda_runtime.h>
#include <cstdint>

// Problem constants (fixed by the reference)
#define H            8
#define NUM_DRAM     4096
#define NUM_HBM      819          // int(4096 * 0.2)
#define TOPK         256
#define PAGE_SIZE    16
#define HEAD_DIM     128
#define PAGE_ELEMS   4096         // 16 * 2 * 128
#define SEQ_PER_HEAD (NUM_HBM * PAGE_SIZE)              // 13104
#define KELEMS_HEAD  ((size_t)SEQ_PER_HEAD * HEAD_DIM)  // 1,677,312
#define KTOTAL       ((size_t)H * KELEMS_HEAD)          // 13,418,496
#define NPAGES       (H * NUM_HBM)                      // 6552

#define GRID_BLOCKS    1184       // 148 SMs * 8 blocks: co-resident, one wave
#define CHUNKS_PER_H   26         // 26 chunks x 32 slots >= 819
#define NCHUNK         (H * CHUNKS_PER_H)   // 208 setup chunks (= setup blocks)
#define SLOTS_PER_WARP 4          // 8 warps * 4 = 32 slots per setup block
#define FLAG_STRIDE    32         // 128B: one L2 line per chunk flag
#define MAXPAGES       6          // ceil(6552/1184)

// Scratch (device globals: allocation-free; flags monotonic => replay-safe)
__device__ int      g_src_page[NPAGES];             // -1 => keep hbm page
__device__ unsigned g_flag[NCHUNK * FLAG_STRIDE];   // per-chunk publish flags

// ---------------------------------------------------------------------------
// ONE persistent kernel, NO global barrier.
//
// R8-R11 lesson: any grid-wide release makes every copy byte wait on the
// globally slowest setup block AND synchronizes 1184 blocks' first LDG burst
// (cross-CTA L1tex-queue contention, ~1.3-2x latency inflation). Here each
// setup chunk (32 slots) publishes its own monotonic flag when done; a copy
// block polls only the flags covering ITS OWN pages. Copy traffic starts as
// soon as the first chunks land (~2.5us), staggered chunk-by-chunk.
//
// Per-replay flag target: each block captures flag_init for its pages at its
// FIRST instructions (launch ramp ~1us << setup's first flag write >=2.5us,
// the same pre-release-capture assumption R9-R11 passed on); target = init+1.
// Flags never reset => deterministic across CUDA-graph replays.
//
// Setup emulates the reference exactly, incl. JAX's negative-index WRAPPING
// in scatters (idx=-1 -> slot 818, applied before mode='drop'):
//   slot = d2h[topk];  pat[slot>=0 ? slot : 818] = step_f
//   stable rank(i) over pat; slot i is a victim iff rank(i) < n_miss,
//   receiving the page of the rank(i)-th miss (inverse of order[] scatter).
//   Hits scatter to wrapped slot 818, last hit wins (818 is never a victim:
//   pat[818]==step_f puts its rank above any possible n_miss).
// ---------------------------------------------------------------------------
__global__ void __launch_bounds__(256, 8) lru_fused_kernel(
    const float* __restrict__ dram,
    const float* __restrict__ hbm,
    const float* __restrict__ pat_g,
    const int*   __restrict__ d2h_g,
    const int*   __restrict__ topk_g,
    const int*   __restrict__ step_g,
    float*       __restrict__ kout,
    float*       __restrict__ vout)
{
    __shared__ float    pat_s[NUM_HBM];
    __shared__ int      miss_page[TOPK];
    __shared__ int      warp_pre[TOPK / 32];
    __shared__ int      n_miss_s, last_hit_s, last_hit_page_s;
    __shared__ unsigned flag_init[MAXPAGES];
    __shared__ unsigned own_flag_s;
    __shared__ int      sp_s;

    const int b    = blockIdx.x;
    const int t    = threadIdx.x;
    const int warp = t >> 5;
    const int lane = t & 31;

    // ---- FIRST instructions: capture pre-release flag values (plain loads)
    if (t < MAXPAGES) {
        const int pid = b + t * GRID_BLOCKS;
        if (pid < NPAGES) {
            const int h = pid / NUM_HBM;
            const int s = pid - h * NUM_HBM;
            const int c = h * CHUNKS_PER_H + (s >> 5);
            flag_init[t] = *((volatile unsigned*)&g_flag[c * FLAG_STRIDE]);
        }
    }
    if (t == 0 && b < NCHUNK)
        own_flag_s = *((volatile unsigned*)&g_flag[b * FLAG_STRIDE]);
    __syncthreads();

    // ---------------- Phase 1: setup (blocks 0..207 == chunk b) -----------
    if (b < NCHUNK) {
        const int h     = b / CHUNKS_PER_H;
        const int chunk = b - h * CHUNKS_PER_H;
        const float step_f = (float)(step_g[0] + 1);

        if (t == 0) { last_hit_s = -1; last_hit_page_s = -1; }
        for (int i = t; i < NUM_HBM; i += 256)
            pat_s[i] = pat_g[h * NUM_HBM + i];

        // Each thread owns one topk entry
        const int p    = topk_g[h * TOPK + t];
        const int slot = d2h_g[h * NUM_DRAM + p];
        const bool miss = (slot < 0);
        const unsigned mm = __ballot_sync(0xFFFFFFFFu, miss);
        const int wpre = __popc(mm & ((1u << lane) - 1u));
        if (lane == 0) warp_pre[warp] = __popc(mm);
        if (!miss) atomicMax(&last_hit_s, t);
        __syncthreads();

        // pat scatter with wrapped negative index (all writes = step_f)
        pat_s[miss ? (NUM_HBM - 1) : slot] = step_f;
        if (t == 0) {
            int c = 0;
            #pragma unroll
            for (int w = 0; w < TOPK / 32; w++) { const int x = warp_pre[w]; warp_pre[w] = c; c += x; }
            n_miss_s = c;
        }
        __syncthreads();

        if (miss) miss_page[warp_pre[warp] + wpre] = p;
        if (t == last_hit_s) last_hit_page_s = p;
        __syncthreads();

        // Each warp ranks 4 slots of this chunk in one sweep over pat_s.
        float vi[SLOTS_PER_WARP];
        int   r [SLOTS_PER_WARP];
        int   idx[SLOTS_PER_WARP];
        #pragma unroll
        for (int q = 0; q < SLOTS_PER_WARP; q++) {
            idx[q] = chunk * 32 + warp * SLOTS_PER_WARP + q;
            vi[q]  = (idx[q] < NUM_HBM) ? pat_s[idx[q]] : 0.0f;
            r[q]   = 0;
        }
        #pragma unroll 2
        for (int j = lane; j < NUM_HBM; j += 32) {
            const float vj = pat_s[j];
            #pragma unroll
            for (int q = 0; q < SLOTS_PER_WARP; q++)
                r[q] += (vj < vi[q]) || (vj == vi[q] && j < idx[q]);
        }
        #pragma unroll
        for (int q = 0; q < SLOTS_PER_WARP; q++) {
            const int rq = __reduce_add_sync(0xFFFFFFFFu, r[q]);
            if (lane == 0 && idx[q] < NUM_HBM) {
                int sp = (rq < n_miss_s) ? miss_page[rq] : -1;
                if (idx[q] == NUM_HBM - 1 && last_hit_page_s >= 0) sp = last_hit_page_s;
                g_src_page[h * NUM_HBM + idx[q]] = sp;
            }
        }
        __syncthreads();           // all 32 entries of this chunk written

        if (t == 0) {
            __threadfence();       // release entries before publishing
            *((volatile unsigned*)&g_flag[b * FLAG_STRIDE]) = own_flag_s + 1u;
        }
    }

    // ---------------- Phase 2: per-page wait + de-interleaving copy --------
    // src elem e = row*256 + kv*128 + d  ->  k/v[h, s*16+row, d].
    int j = 0;
    for (int pid = b; pid < NPAGES; pid += GRID_BLOCKS, j++) {
        const int h = pid / NUM_HBM;
        const int s = pid - h * NUM_HBM;

        if (t == 0) {
            const int c = h * CHUNKS_PER_H + (s >> 5);
            volatile unsigned* f = &g_flag[c * FLAG_STRIDE];
            const unsigned tgt = flag_init[j] + 1u;
            while (*f < tgt) __nanosleep(128);
            __threadfence();                       // acquire entries
            sp_s = __ldcg(&g_src_page[pid]);
        }
        __syncthreads();
        const int sp = sp_s;
        __syncthreads();                           // sp consumed before reuse

        const float4* __restrict__ src = (const float4*)(
            (sp >= 0) ? (dram + ((size_t)h * NUM_DRAM + (size_t)sp) * PAGE_ELEMS)
                      : (hbm  + (size_t)pid * PAGE_ELEMS));

        float4* __restrict__ kbase =
            (float4*)(kout + ((size_t)h * SEQ_PER_HEAD + (size_t)s * PAGE_SIZE) * HEAD_DIM);
        float4* __restrict__ vbase =
            (float4*)(vout + ((size_t)h * SEQ_PER_HEAD + (size_t)s * PAGE_SIZE) * HEAD_DIM);

        // 1024 float4 per page; 4 independent 16B ops per thread (MLP=4).
        #pragma unroll
        for (int u = 0; u < 4; u++) {
            const int f4 = t + u * 256;
            const float4 val = src[f4];
            const int row = f4 >> 6;
            const int dd  = f4 & 31;
            if ((f4 >> 5) & 1) vbase[row * 32 + dd] = val;
            else               kbase[row * 32 + dd] = val;
        }
    }
}

// ---------------------------------------------------------------------------
// Launch: single kernel, graph-capture friendly, allocation-free.
// ---------------------------------------------------------------------------
extern "C" void kernel_launch(void* const* d_in, const int* in_sizes, int n_in,
                              void* d_out, int out_size)
{
    const float* dram = (const float*)d_in[0];   // (H, 4096, 4096) f32
    const float* hbm  = (const float*)d_in[1];   // (H, 819, 4096)  f32
    const float* pat  = (const float*)d_in[2];   // (H, 819)        f32
    const int*   d2h  = (const int*)  d_in[3];   // (H, 4096)       i32
    // d_in[4] = h2d (never affects the returned k/v caches)
    const int*   topk = (const int*)  d_in[5];   // (H, 256)        i32
    const int*   step = (const int*)  d_in[6];   // (1,)            i32

    float* kout = (float*)d_out;
    float* vout = (float*)d_out + KTOTAL;

    lru_fused_kernel<<<GRID_BLOCKS, 256>>>(dram, hbm, pat, d2h, topk, step, kout, vout);
}

// round 13
// speedup vs baseline: 1.0957x; 1.0748x over previous
#include <cuda_runtime.h>
#include <cstdint>

// Problem constants (fixed by the reference)
#define H            8
#define NUM_DRAM     4096
#define NUM_HBM      819          // int(4096 * 0.2)
#define TOPK         256
#define PAGE_SIZE    16
#define HEAD_DIM     128
#define PAGE_ELEMS   4096         // 16 * 2 * 128
#define SEQ_PER_HEAD (NUM_HBM * PAGE_SIZE)              // 13104
#define KELEMS_HEAD  ((size_t)SEQ_PER_HEAD * HEAD_DIM)  // 1,677,312
#define KTOTAL       ((size_t)H * KELEMS_HEAD)          // 13,418,496

#define SLOTS_PER_WARP 4
#define SLOTS_PER_BLK  32         // 8 warps * 4 slots
#define CHUNKS         ((NUM_HBM + SLOTS_PER_BLK - 1) / SLOTS_PER_BLK)   // 26

// Scratch: for each (head, hbm_slot), the DRAM page to pull in (-1 => keep hbm page)
__device__ int g_src_page[H * NUM_HBM];

// ---------------------------------------------------------------------------
// Setup kernel. grid=(H, 26), block=256 (8 warps x 4 slots, one sweep).
//
// Emulates the reference exactly, incl. JAX's negative-index WRAPPING in
// scatters (idx=-1 -> slot 818, applied before mode='drop'):
//   slot = d2h[topk];  pat[slot>=0 ? slot : 818] = step_f
//   stable rank(i) over pat;  slot i is a victim iff rank(i) < n_miss,
//   receiving the page of the rank(i)-th miss (inverse of order[] scatter).
//   Hits scatter to wrapped slot 818, last hit wins (818 is never a victim:
//   pat[818]==step_f puts its rank above any possible n_miss).
// ---------------------------------------------------------------------------
__global__ void lru_setup_kernel(const float* __restrict__ pat_g,
                                 const int*   __restrict__ d2h_g,
                                 const int*   __restrict__ topk_g,
                                 const int*   __restrict__ step_g)
{
    __shared__ float pat_s[NUM_HBM];
    __shared__ int   miss_page[TOPK];
    __shared__ int   warp_pre[TOPK / 32];
    __shared__ int   n_miss_s, last_hit_s, last_hit_page_s;

    const int h     = blockIdx.x;
    const int chunk = blockIdx.y;
    const int t     = threadIdx.x;       // 0..255
    const int warp  = t >> 5;
    const int lane  = t & 31;
    const float step_f = (float)(step_g[0] + 1);

    if (t == 0) { last_hit_s = -1; last_hit_page_s = -1; }
    for (int i = t; i < NUM_HBM; i += 256)
        pat_s[i] = pat_g[h * NUM_HBM + i];

    // Every thread owns one topk entry
    const int p    = topk_g[h * TOPK + t];
    const int slot = d2h_g[h * NUM_DRAM + p];
    const bool miss = (slot < 0);
    const unsigned mm = __ballot_sync(0xFFFFFFFFu, miss);
    const int wpre = __popc(mm & ((1u << lane) - 1u));
    if (lane == 0) warp_pre[warp] = __popc(mm);
    if (!miss) atomicMax(&last_hit_s, t);
    __syncthreads();

    // pat scatter with wrapped negative index (all writes = step_f; races benign)
    pat_s[miss ? (NUM_HBM - 1) : slot] = step_f;
    if (t == 0) {                        // scan the 8 warp miss-counts
        int c = 0;
        #pragma unroll
        for (int w = 0; w < TOPK / 32; w++) { const int x = warp_pre[w]; warp_pre[w] = c; c += x; }
        n_miss_s = c;
    }
    __syncthreads();

    if (miss) miss_page[warp_pre[warp] + wpre] = p;
    if (t == last_hit_s) last_hit_page_s = p;
    __syncthreads();

    // Each warp ranks 4 slots of this chunk in ONE sweep over pat_s
    // (4 independent compare chains per lane -> good ILP, 26 LDS iters total).
    float vi[SLOTS_PER_WARP];
    int   r [SLOTS_PER_WARP];
    int   idx[SLOTS_PER_WARP];
    #pragma unroll
    for (int q = 0; q < SLOTS_PER_WARP; q++) {
        idx[q] = chunk * SLOTS_PER_BLK + warp * SLOTS_PER_WARP + q;
        vi[q]  = (idx[q] < NUM_HBM) ? pat_s[idx[q]] : 0.0f;
        r[q]   = 0;
    }
    #pragma unroll 2
    for (int j = lane; j < NUM_HBM; j += 32) {
        const float vj = pat_s[j];
        #pragma unroll
        for (int q = 0; q < SLOTS_PER_WARP; q++)
            r[q] += (vj < vi[q]) || (vj == vi[q] && j < idx[q]);
    }
    #pragma unroll
    for (int q = 0; q < SLOTS_PER_WARP; q++) {
        const int rq = __reduce_add_sync(0xFFFFFFFFu, r[q]);
        if (lane == 0 && idx[q] < NUM_HBM) {
            int sp = (rq < n_miss_s) ? miss_page[rq] : -1;
            if (idx[q] == NUM_HBM - 1 && last_hit_page_s >= 0) sp = last_hit_page_s;
            g_src_page[h * NUM_HBM + idx[q]] = sp;
        }
    }
}

// ---------------------------------------------------------------------------
// Bulk de-interleaving copy — byte-identical to the proven 30.1us version.
// One block per (head, hbm_slot) page.
// src elem e = row*256 + kv*128 + d  ->  k/v[h, s*16+row, d].
// Plain LDG/STG.128, 512B coalesced segments.
// ---------------------------------------------------------------------------
__global__ void page_copy_kernel(const float* __restrict__ dram,
                                 const float* __restrict__ hbm,
                                 float*       __restrict__ kout,
                                 float*       __restrict__ vout)
{
    const int page_id = blockIdx.x;            // 0 .. H*NUM_HBM-1
    const int h = page_id / NUM_HBM;
    const int s = page_id - h * NUM_HBM;

    const int sp = g_src_page[page_id];
    const float4* __restrict__ src = (const float4*)(
        (sp >= 0) ? (dram + ((size_t)h * NUM_DRAM + (size_t)sp) * PAGE_ELEMS)
                  : (hbm  + (size_t)page_id * PAGE_ELEMS));

    float4* __restrict__ kbase =
        (float4*)(kout + ((size_t)h * SEQ_PER_HEAD + (size_t)s * PAGE_SIZE) * HEAD_DIM);
    float4* __restrict__ vbase =
        (float4*)(vout + ((size_t)h * SEQ_PER_HEAD + (size_t)s * PAGE_SIZE) * HEAD_DIM);

    // 1024 float4 per page; 4 independent 16B ops per thread (MLP=4).
    #pragma unroll 4
    for (int f = threadIdx.x; f < PAGE_ELEMS / 4; f += 256) {
        const float4 val = src[f];
        const int row = f >> 6;
        const int dd  = f & 31;
        if ((f >> 5) & 1) vbase[row * 32 + dd] = val;
        else              kbase[row * 32 + dd] = val;
    }
}

// ---------------------------------------------------------------------------
// Launch: two plain kernels (PDL attrs measured as a net loss in R6/R7).
// ---------------------------------------------------------------------------
extern "C" void kernel_launch(void* const* d_in, const int* in_sizes, int n_in,
                              void* d_out, int out_size)
{
    const float* dram = (const float*)d_in[0];   // (H, 4096, 4096) f32
    const float* hbm  = (const float*)d_in[1];   // (H, 819, 4096)  f32
    const float* pat  = (const float*)d_in[2];   // (H, 819)        f32
    const int*   d2h  = (const int*)  d_in[3];   // (H, 4096)       i32
    // d_in[4] = h2d (never affects the returned k/v caches)
    const int*   topk = (const int*)  d_in[5];   // (H, 256)        i32
    const int*   step = (const int*)  d_in[6];   // (1,)            i32

    float* kout = (float*)d_out;
    float* vout = (float*)d_out + KTOTAL;

    lru_setup_kernel<<<dim3(H, CHUNKS), 256>>>(pat, d2h, topk, step);
    page_copy_kernel<<<H * NUM_HBM, 256>>>(dram, hbm, kout, vout);
}

// round 14
// speedup vs baseline: 1.1462x; 1.0461x over previous
#include <cuda_runtime.h>
#include <cstdint>

// Problem constants (fixed by the reference)
#define H            8
#define NUM_DRAM     4096
#define NUM_HBM      819          // int(4096 * 0.2)
#define TOPK         256
#define PAGE_SIZE    16
#define HEAD_DIM     128
#define PAGE_ELEMS   4096         // 16 * 2 * 128
#define SEQ_PER_HEAD (NUM_HBM * PAGE_SIZE)              // 13104
#define KELEMS_HEAD  ((size_t)SEQ_PER_HEAD * HEAD_DIM)  // 1,677,312
#define KTOTAL       ((size_t)H * KELEMS_HEAD)          // 13,418,496
#define NPAGES       (H * NUM_HBM)                      // 6552 (even)

#define SLOTS_PER_BLK 32          // one warp per slot, 32 warps per block
#define CHUNKS        ((NUM_HBM + SLOTS_PER_BLK - 1) / SLOTS_PER_BLK)   // 26

// Scratch: for each (head, hbm_slot), the DRAM page to pull in (-1 => keep hbm page)
__device__ int g_src_page[NPAGES];

// ---------------------------------------------------------------------------
// Setup kernel — R4's measured-best shape, verbatim logic.
// grid=(H, 26), block=1024 (one warp per slot).
//
// Emulates the reference exactly, incl. JAX's negative-index WRAPPING in
// scatters (idx=-1 -> slot 818, applied before mode='drop'):
//   slot = d2h[topk];  pat[slot>=0 ? slot : 818] = step_f
//   stable rank(i) over pat;  slot i is a victim iff rank(i) < n_miss,
//   receiving the page of the rank(i)-th miss (inverse of order[] scatter).
//   Hits scatter to wrapped slot 818, last hit wins (818 is never a victim:
//   pat[818]==step_f puts its rank above any possible n_miss).
// ---------------------------------------------------------------------------
__global__ void __launch_bounds__(1024) lru_setup_kernel(
    const float* __restrict__ pat_g,
    const int*   __restrict__ d2h_g,
    const int*   __restrict__ topk_g,
    const int*   __restrict__ step_g)
{
    __shared__ float pat_s[NUM_HBM];
    __shared__ int   topk_s[TOPK];
    __shared__ int   slot_s[TOPK];
    __shared__ int   miss_page[TOPK];
    __shared__ int   warp_pre[TOPK / 32];
    __shared__ int   n_miss_s, last_hit_s, last_hit_page_s;

    const int h    = blockIdx.x;
    const int t    = threadIdx.x;
    const int warp = t >> 5;
    const int lane = t & 31;
    const float step_f = (float)(step_g[0] + 1);

    if (t == 0) { last_hit_s = -1; last_hit_page_s = -1; }
    for (int i = t; i < NUM_HBM; i += 1024)
        pat_s[i] = pat_g[h * NUM_HBM + i];

    bool miss = false;
    int  wpre = 0;
    if (t < TOPK) {
        const int p = topk_g[h * TOPK + t];
        topk_s[t] = p;
        const int slot = d2h_g[h * NUM_DRAM + p];
        slot_s[t] = slot;
        miss = (slot < 0);
        const unsigned mm = __ballot_sync(0xFFFFFFFFu, miss);
        wpre = __popc(mm & ((1u << lane) - 1u));
        if (lane == 0) warp_pre[warp] = __popc(mm);
        if (!miss) atomicMax(&last_hit_s, t);
    }
    __syncthreads();

    // pat scatter with wrapped negative index (all writes = step_f; races benign)
    if (t < TOPK) pat_s[miss ? (NUM_HBM - 1) : slot_s[t]] = step_f;
    if (t == 0) {
        int c = 0;
        #pragma unroll
        for (int w = 0; w < TOPK / 32; w++) { const int x = warp_pre[w]; warp_pre[w] = c; c += x; }
        n_miss_s = c;
    }
    __syncthreads();

    if (t < TOPK && miss) miss_page[warp_pre[warp] + wpre] = topk_s[t];
    if (t == last_hit_s)  last_hit_page_s = topk_s[t];
    __syncthreads();

    // One warp per slot: stable rank(i) = #{j: pat[j]<pat[i] || (== && j<i)}
    const int i = blockIdx.y * SLOTS_PER_BLK + warp;
    if (i < NUM_HBM) {
        const float vi = pat_s[i];
        int r = 0;
        #pragma unroll 2
        for (int j = lane; j < NUM_HBM; j += 32) {
            const float vj = pat_s[j];
            r += (vj < vi) || (vj == vi && j < i);
        }
        r = __reduce_add_sync(0xFFFFFFFFu, r);
        if (lane == 0) {
            int sp = (r < n_miss_s) ? miss_page[r] : -1;
            if (i == NUM_HBM - 1 && last_hit_page_s >= 0) sp = last_hit_page_s;
            g_src_page[h * NUM_HBM + i] = sp;
        }
    }
}

// ---------------------------------------------------------------------------
// Bulk de-interleaving copy: TWO pages per block, all 8 independent 16B loads
// issued before any store (MLP_p1=8 per thread — the copy is latency-limited
// at 68% DRAM / 13% issue, so deeper per-warp MLP is the remaining knob).
// src elem e = row*256 + kv*128 + d  ->  k/v[h, s*16+row, d].
// ---------------------------------------------------------------------------
__global__ void __launch_bounds__(256) page_copy_kernel(
    const float* __restrict__ dram,
    const float* __restrict__ hbm,
    float*       __restrict__ kout,
    float*       __restrict__ vout)
{
    const int t    = threadIdx.x;
    const int pid0 = blockIdx.x * 2;           // NPAGES is even
    const int pid1 = pid0 + 1;

    const int h0 = pid0 / NUM_HBM, s0 = pid0 - h0 * NUM_HBM;
    const int h1 = pid1 / NUM_HBM, s1 = pid1 - h1 * NUM_HBM;

    const int sp0 = g_src_page[pid0];
    const int sp1 = g_src_page[pid1];

    const float4* __restrict__ src0 = (const float4*)(
        (sp0 >= 0) ? (dram + ((size_t)h0 * NUM_DRAM + (size_t)sp0) * PAGE_ELEMS)
                   : (hbm  + (size_t)pid0 * PAGE_ELEMS));
    const float4* __restrict__ src1 = (const float4*)(
        (sp1 >= 0) ? (dram + ((size_t)h1 * NUM_DRAM + (size_t)sp1) * PAGE_ELEMS)
                   : (hbm  + (size_t)pid1 * PAGE_ELEMS));

    float4* __restrict__ kb0 =
        (float4*)(kout + ((size_t)h0 * SEQ_PER_HEAD + (size_t)s0 * PAGE_SIZE) * HEAD_DIM);
    float4* __restrict__ vb0 =
        (float4*)(vout + ((size_t)h0 * SEQ_PER_HEAD + (size_t)s0 * PAGE_SIZE) * HEAD_DIM);
    float4* __restrict__ kb1 =
        (float4*)(kout + ((size_t)h1 * SEQ_PER_HEAD + (size_t)s1 * PAGE_SIZE) * HEAD_DIM);
    float4* __restrict__ vb1 =
        (float4*)(vout + ((size_t)h1 * SEQ_PER_HEAD + (size_t)s1 * PAGE_SIZE) * HEAD_DIM);

    // 8 independent loads first (front-batched), then 8 stores.
    float4 v[8];
    #pragma unroll
    for (int u = 0; u < 4; u++) v[u]     = src0[t + u * 256];
    #pragma unroll
    for (int u = 0; u < 4; u++) v[4 + u] = src1[t + u * 256];

    #pragma unroll
    for (int u = 0; u < 4; u++) {
        const int f   = t + u * 256;
        const int row = f >> 6;
        const int dd  = f & 31;
        if ((f >> 5) & 1) vb0[row * 32 + dd] = v[u];
        else              kb0[row * 32 + dd] = v[u];
    }
    #pragma unroll
    for (int u = 0; u < 4; u++) {
        const int f   = t + u * 256;
        const int row = f >> 6;
        const int dd  = f & 31;
        if ((f >> 5) & 1) vb1[row * 32 + dd] = v[4 + u];
        else              kb1[row * 32 + dd] = v[4 + u];
    }
}

// ---------------------------------------------------------------------------
// Launch: two plain kernels (PDL / fused variants all measured slower).
// ---------------------------------------------------------------------------
extern "C" void kernel_launch(void* const* d_in, const int* in_sizes, int n_in,
                              void* d_out, int out_size)
{
    const float* dram = (const float*)d_in[0];   // (H, 4096, 4096) f32
    const float* hbm  = (const float*)d_in[1];   // (H, 819, 4096)  f32
    const float* pat  = (const float*)d_in[2];   // (H, 819)        f32
    const int*   d2h  = (const int*)  d_in[3];   // (H, 4096)       i32
    // d_in[4] = h2d (never affects the returned k/v caches)
    const int*   topk = (const int*)  d_in[5];   // (H, 256)        i32
    const int*   step = (const int*)  d_in[6];   // (1,)            i32

    float* kout = (float*)d_out;
    float* vout = (float*)d_out + KTOTAL;

    lru_setup_kernel<<<dim3(H, CHUNKS), 1024>>>(pat, d2h, topk, step);
    page_copy_kernel<<<NPAGES / 2, 256>>>(dram, hbm, kout, vout);
}